// round 6
// baseline (speedup 1.0000x reference)
#include <cuda_runtime.h>

// CrossEntropyLossWithGaussianSmoothedLabels
// pred: (32, 2048, 722) fp32, target: (32, 2048) int32 -> scalar mean loss.
//
// loss(row) = W * log(sum_c exp(pred[c])) - sum_k w_k * pred[base+k]
// Two adjacent rows per warp: 1444 floats = 361 float4, 16B-aligned
// (5776-byte pair stride), so the bulk pass is pure coalesced LDG.128.

#define NUM_CLASSES 722
#define WARPS_PER_BLOCK 8

__global__ void init_out_kernel(float* out) { out[0] = 0.0f; }

__global__ __launch_bounds__(WARPS_PER_BLOCK * 32)
void ce_smoothed2_kernel(const float* __restrict__ pred,
                         const int* __restrict__ target,
                         float* __restrict__ out,
                         int n_rows) {
    __shared__ float blk_acc;
    const int tid  = threadIdx.x;
    const int warp = tid >> 5;
    const int lane = tid & 31;

    if (tid == 0) blk_acc = 0.0f;
    __syncthreads();

    const int pair    = blockIdx.x * WARPS_PER_BLOCK + warp;
    const int n_pairs = n_rows >> 1;   // n_rows = 65536 (even)

    if (pair < n_pairs) {
        const float*  base = pred + (size_t)pair * (2 * NUM_CLASSES);
        const float4* p4   = reinterpret_cast<const float4*>(base);

        // ---- streaming exp-sum over both rows (361 aligned float4) ----
        // float4 j<180 -> row0, j>180 -> row1, j==180 -> 2 elems each.
        float s0 = 0.0f, s1 = 0.0f;
#pragma unroll 4
        for (int j = lane; j < 361; j += 32) {
            float4 v = __ldg(&p4[j]);
            float e0 = __expf(v.x), e1 = __expf(v.y);
            float e2 = __expf(v.z), e3 = __expf(v.w);
            if (j < 180)      s0 += (e0 + e1) + (e2 + e3);
            else if (j > 180) s1 += (e0 + e1) + (e2 + e3);
            else            { s0 += e0 + e1;  s1 += e2 + e3; }
        }
        // butterfly: every lane ends with both row sums
#pragma unroll
        for (int o = 16; o > 0; o >>= 1) {
            s0 += __shfl_xor_sync(0xffffffffu, s0, o);
            s1 += __shfl_xor_sync(0xffffffffu, s1, o);
        }
        const float lg0 = __logf(s0);
        const float lg1 = __logf(s1);

        // ---- smoothed-label windows, both rows in parallel ----
        // lanes 0..6 -> row0 window, lanes 8..14 -> row1 window.
        // Reference scatter order (chronological): +3,-3,+2,-2,+1,-1,0,0, t=1.0;
        // reverse-chronological first-match gives the surviving weight.
        float c = 0.0f;
        const int sub = lane >> 3;   // 0: row0 lanes, 1: row1 lanes
        const int ll  = lane & 7;
        if (sub < 2 && ll < 7) {
            const int t = target[2 * pair + sub];
            const float* prow = base + sub * NUM_CLASSES;
            const int idx = max(0, t - 3) + ll;
            float w = 0.0f;
            if (idx < NUM_CLASSES) {
                const float D1 = 0.60653065971263342360f;  // exp(-0.5)
                const float D2 = 0.36787944117144232160f;  // exp(-1)
                const float D3 = 0.13533528323661269189f;  // exp(-2)
                if      (idx == t)                          w = 1.0f;
                else if (idx == max(t - 1, 0))              w = D1;
                else if (idx == min(t + 1, NUM_CLASSES-1))  w = D1;
                else if (idx == max(t - 2, 0))              w = D2;
                else if (idx == min(t + 2, NUM_CLASSES-1))  w = D2;
                else if (idx == max(t - 3, 0))              w = D3;
                else if (idx == min(t + 3, NUM_CLASSES-1))  w = D3;
            }
            if (w != 0.0f) {
                const float lg = sub ? lg1 : lg0;
                c = w * lg - w * prow[idx];   // L2 hit: row just streamed
            }
        }
        // single warp reduction of the combined two-row loss
#pragma unroll
        for (int o = 16; o > 0; o >>= 1)
            c += __shfl_down_sync(0xffffffffu, c, o);

        if (lane == 0) atomicAdd(&blk_acc, c);
    }
    __syncthreads();
    if (tid == 0) {
        atomicAdd(out, blk_acc * (1.0f / (float)n_rows));
    }
}

extern "C" void kernel_launch(void* const* d_in, const int* in_sizes, int n_in,
                              void* d_out, int out_size) {
    const float* pred   = (const float*)d_in[0];
    const int*   target = (const int*)d_in[1];
    float*       out    = (float*)d_out;

    const int n_rows  = in_sizes[1];     // 32*2048 = 65536
    const int n_pairs = n_rows >> 1;     // 32768

    init_out_kernel<<<1, 1>>>(out);

    const int threads = WARPS_PER_BLOCK * 32;
    const int blocks  = (n_pairs + WARPS_PER_BLOCK - 1) / WARPS_PER_BLOCK;
    ce_smoothed2_kernel<<<blocks, threads>>>(pred, target, out, n_rows);
}